// round 14
// baseline (speedup 1.0000x reference)
#include <cuda_runtime.h>
#include <cstdint>

#define FULLM 0xffffffffu
typedef unsigned long long ull;
typedef unsigned int uint;

static __device__ __forceinline__ ull mul2(ull a, ull b){
    ull d; asm("mul.rn.f32x2 %0, %1, %2;" : "=l"(d) : "l"(a), "l"(b)); return d;
}
static __device__ __forceinline__ ull dup2(float x){
    ull d; asm("mov.b64 %0, {%1, %1};" : "=l"(d) : "f"(x)); return d;
}
static __device__ __forceinline__ ull pack2(float a, float b){
    ull d; asm("mov.b64 %0, {%1, %2};" : "=l"(d) : "f"(a), "f"(b)); return d;
}
static __device__ __forceinline__ float2 unpk(ull a){
    float2 f; asm("mov.b64 {%0, %1}, %2;" : "=f"(f.x), "=f"(f.y) : "l"(a)); return f;
}
static __device__ __forceinline__ uint to_tf32(float x){
    uint r; asm("cvt.rna.tf32.f32 %0, %1;" : "=r"(r) : "f"(x)); return r;
}
static __device__ __forceinline__ void mma_tf32(float c[4], const uint a[4], uint b0, uint b1){
    asm("mma.sync.aligned.m16n8k8.row.col.f32.tf32.tf32.f32 "
        "{%0,%1,%2,%3}, {%4,%5,%6,%7}, {%8,%9}, {%0,%1,%2,%3};"
        : "+f"(c[0]), "+f"(c[1]), "+f"(c[2]), "+f"(c[3])
        : "r"(a[0]), "r"(a[1]), "r"(a[2]), "r"(a[3]), "r"(b0), "r"(b1));
}

// softplus via ex2 + lg2 (2 MUFU/elem, off the fma pipe)
static __device__ __forceinline__ float2 softplus2(ull x){
    ull ax; asm("and.b64 %0, %1, 0x7FFFFFFF7FFFFFFF;" : "=l"(ax) : "l"(x));
    ull t = mul2(ax, dup2(-1.4426950408889634f));
    float2 tf = unpk(t);
    float e0, e1;
    asm("ex2.approx.f32 %0, %1;" : "=f"(e0) : "f"(tf.x));
    asm("ex2.approx.f32 %0, %1;" : "=f"(e1) : "f"(tf.y));
    float l0, l1;
    asm("lg2.approx.f32 %0, %1;" : "=f"(l0) : "f"(e0 + 1.0f));
    asm("lg2.approx.f32 %0, %1;" : "=f"(l1) : "f"(e1 + 1.0f));
    float2 xf = unpk(x);
    return make_float2(fmaf(l0, 0.6931471805599453f, fmaxf(xf.x, 0.f)),
                       fmaf(l1, 0.6931471805599453f, fmaxf(xf.y, 0.f)));
}

constexpr int   BN     = 262144;
constexpr int   GROUPS = BN / 32;
constexpr int   HPAD   = 272;
constexpr int   AS     = 36;
constexpr float EPSF   = 1e-12f;

// w3 fragments: [w][ik][j][lane] -> uint4 {bhi0,bhi1,blo0,blo1}
__device__ uint4 g_w3pack[8 * 4 * 4 * 32];
// w0/w1/w2 fragments: L0 [nt][ks(2)][lane] @0, L1 [nt][ks(4)][lane] @256, L2 @768
__device__ uint4 g_wfrag[1280];

__global__ void prep_kernel(const float* __restrict__ w3, const float* __restrict__ w0,
                            const float* __restrict__ w1, const float* __restrict__ w2) {
    int idx = blockIdx.x * blockDim.x + threadIdx.x;
    int lane = idx & 31;
    int gid = lane >> 2, tig = lane & 3;
    if (idx < 4096) {
        int j = (idx >> 5) & 3, ik = (idx >> 7) & 3, w = idx >> 9;
        int n0 = w * 32;
        float v0 = w3[(ik*8 + tig    )*256 + n0 + j*8 + gid];
        float v1 = w3[(ik*8 + tig + 4)*256 + n0 + j*8 + gid];
        uint h0 = to_tf32(v0), h1 = to_tf32(v1);
        g_w3pack[idx] = make_uint4(h0, h1, to_tf32(v0 - __uint_as_float(h0)),
                                           to_tf32(v1 - __uint_as_float(h1)));
    } else if (idx < 4096 + 256) {
        int t = idx - 4096;
        int ks = (t >> 5) & 1, nt = t >> 6;
        int n = nt*8 + gid;
        int ka = ks*8 + tig, kb = ks*8 + tig + 4;
        float v0 = (ka < 10) ? w0[ka*32 + n] : 0.f;
        float v1 = (kb < 10) ? w0[kb*32 + n] : 0.f;
        uint h0 = to_tf32(v0), h1 = to_tf32(v1);
        g_wfrag[t] = make_uint4(h0, h1, to_tf32(v0 - __uint_as_float(h0)),
                                        to_tf32(v1 - __uint_as_float(h1)));
    } else if (idx < 4096 + 256 + 1024) {
        int t = idx - 4096 - 256;
        const float* W = (t < 512) ? w1 : w2;
        int tt = t & 511;
        int ks = (tt >> 5) & 3, nt = tt >> 7;
        int n = nt*8 + gid;
        float v0 = W[(ks*8 + tig    )*32 + n];
        float v1 = W[(ks*8 + tig + 4)*32 + n];
        uint h0 = to_tf32(v0), h1 = to_tf32(v1);
        g_wfrag[256 + t] = make_uint4(h0, h1, to_tf32(v0 - __uint_as_float(h0)),
                                              to_tf32(v1 - __uint_as_float(h1)));
    }
}

__global__ __launch_bounds__(256, 4)
void hist2d_kernel(const float* __restrict__ wi, const float* __restrict__ cond,
                   const float* __restrict__ b0, const float* __restrict__ b1,
                   const float* __restrict__ b2, const float* __restrict__ b3,
                   float* __restrict__ out)
{
    __shared__ __align__(16) float bufA[32 * AS];
    __shared__ __align__(16) float bufB[32 * AS];
    __shared__ float s_rows[32][17];
    __shared__ __align__(16) float s_hist[32][HPAD];

    const int tid  = threadIdx.x;
    const int lane = tid & 31;
    const int w    = tid >> 5;
    const int gid  = lane >> 2;
    const int tig  = lane & 3;
    const int mt   = (w & 1) * 16;
    const int nt   = w >> 1;
    const int n8   = nt * 8;
    const int n0   = w * 32;

    const uint4* f0 = &g_wfrag[nt*64 + lane];
    const uint4* f1 = &g_wfrag[256 + nt*128 + lane];
    const uint4* f2 = &g_wfrag[768 + nt*128 + lane];
    const uint4* fragp = &g_w3pack[(w * 16) * 32 + lane];

    // one MLP layer (m16n8 tile per warp) via 3xTF32 mma, relu, write to dst.
    // bias reloaded via __ldg (L1) to keep persistent registers minimal.
    auto layer = [&](const float* src, float* dst, const uint4* wf, const float* bvec, int ksteps) {
        float c[4] = {0.f, 0.f, 0.f, 0.f};
        #pragma unroll 4
        for (int ks = 0; ks < ksteps; ++ks) {
            const int k0 = ks * 8;
            float a0 = src[(mt + gid    ) * AS + k0 + tig    ];
            float a1 = src[(mt + gid + 8) * AS + k0 + tig    ];
            float a2 = src[(mt + gid    ) * AS + k0 + tig + 4];
            float a3 = src[(mt + gid + 8) * AS + k0 + tig + 4];
            uint ah[4], al[4];
            ah[0] = to_tf32(a0); al[0] = to_tf32(a0 - __uint_as_float(ah[0]));
            ah[1] = to_tf32(a1); al[1] = to_tf32(a1 - __uint_as_float(ah[1]));
            ah[2] = to_tf32(a2); al[2] = to_tf32(a2 - __uint_as_float(ah[2]));
            ah[3] = to_tf32(a3); al[3] = to_tf32(a3 - __uint_as_float(ah[3]));
            uint4 f = __ldg(&wf[ks * 32]);
            mma_tf32(c, ah, f.x, f.y);
            mma_tf32(c, ah, f.z, f.w);
            mma_tf32(c, al, f.x, f.y);
        }
        float bx = __ldg(&bvec[n8 + 2*tig]);
        float by = __ldg(&bvec[n8 + 2*tig + 1]);
        c[0] = fmaxf(c[0] + bx, 0.f);
        c[1] = fmaxf(c[1] + by, 0.f);
        c[2] = fmaxf(c[2] + bx, 0.f);
        c[3] = fmaxf(c[3] + by, 0.f);
        *(float2*)&dst[(mt + gid    ) * AS + n8 + 2*tig] = make_float2(c[0], c[1]);
        *(float2*)&dst[(mt + gid + 8) * AS + n8 + 2*tig] = make_float2(c[2], c[3]);
    };

    for (int g = blockIdx.x; g < GROUPS; g += gridDim.x) {
        const int Sblk = g * 32;

        // ---- load cond into bufA + zero-pad K 10..15 ----
        #pragma unroll
        for (int i = tid; i < 320; i += 256) bufA[(i/10)*AS + (i%10)] = __ldg(&cond[Sblk*10 + i]);
        if (tid < 192) bufA[(tid/6)*AS + 10 + (tid%6)] = 0.f;
        __syncthreads();

        layer(bufA, bufB, f0, b0, 2);
        __syncthreads();
        layer(bufB, bufA, f1, b1, 4);
        __syncthreads();
        layer(bufA, bufB, f2, b2, 4);
        __syncthreads();

        // ============ Phase B: layer 3, im-outer (small accumulator live range) ============
        #pragma unroll
        for (int im = 0; im < 2; ++im) {
            float c[4][4];
            #pragma unroll
            for (int j = 0; j < 4; ++j) {
                float bx = __ldg(&b3[n0 + j*8 + 2*tig]);
                float by = __ldg(&b3[n0 + j*8 + 2*tig + 1]);
                c[j][0] = bx; c[j][1] = by; c[j][2] = bx; c[j][3] = by;
            }

            const int r0 = im * 16 + gid;
            #pragma unroll
            for (int ik = 0; ik < 4; ++ik) {
                const int k0 = ik * 8;
                float a0 = bufB[ r0      * AS + k0 + tig    ];
                float a1 = bufB[(r0 + 8) * AS + k0 + tig    ];
                float a2 = bufB[ r0      * AS + k0 + tig + 4];
                float a3 = bufB[(r0 + 8) * AS + k0 + tig + 4];
                uint ah[4], al[4];
                ah[0] = to_tf32(a0); al[0] = to_tf32(a0 - __uint_as_float(ah[0]));
                ah[1] = to_tf32(a1); al[1] = to_tf32(a1 - __uint_as_float(ah[1]));
                ah[2] = to_tf32(a2); al[2] = to_tf32(a2 - __uint_as_float(ah[2]));
                ah[3] = to_tf32(a3); al[3] = to_tf32(a3 - __uint_as_float(ah[3]));
                #pragma unroll
                for (int j = 0; j < 4; ++j) {
                    uint4 f = __ldg(&fragp[(ik*4 + j) * 32]);
                    mma_tf32(c[j], ah, f.x, f.y);
                    mma_tf32(c[j], ah, f.z, f.w);
                    mma_tf32(c[j], al, f.x, f.y);
                }
            }

            // epilogue for this im: softplus, hist writes, row sums
            const int m0 = im * 16 + gid;
            float rs_lo0 = 0.f, rs_hi0 = 0.f, rs_lo8 = 0.f, rs_hi8 = 0.f;
            #pragma unroll
            for (int j = 0; j < 4; ++j) {
                float2 s01 = softplus2(pack2(c[j][0], c[j][1]));
                float2 s23 = softplus2(pack2(c[j][2], c[j][3]));
                const int colb = n0 + j*8 + 2*tig;
                *(float2*)&s_hist[m0    ][colb] = s01;
                *(float2*)&s_hist[m0 + 8][colb] = s23;
                float t0 = s01.x + s01.y;
                float t8 = s23.x + s23.y;
                if (j < 2) { rs_lo0 += t0; rs_lo8 += t8; }
                else       { rs_hi0 += t0; rs_hi8 += t8; }
            }
            rs_lo0 += __shfl_xor_sync(FULLM, rs_lo0, 1);
            rs_hi0 += __shfl_xor_sync(FULLM, rs_hi0, 1);
            rs_lo8 += __shfl_xor_sync(FULLM, rs_lo8, 1);
            rs_hi8 += __shfl_xor_sync(FULLM, rs_hi8, 1);
            rs_lo0 += __shfl_xor_sync(FULLM, rs_lo0, 2);
            rs_hi0 += __shfl_xor_sync(FULLM, rs_hi0, 2);
            rs_lo8 += __shfl_xor_sync(FULLM, rs_lo8, 2);
            rs_hi8 += __shfl_xor_sync(FULLM, rs_hi8, 2);
            if (tig == 0) {
                s_rows[m0    ][2*w    ] = rs_lo0;
                s_rows[m0    ][2*w + 1] = rs_hi0;
                s_rows[m0 + 8][2*w    ] = rs_lo8;
                s_rows[m0 + 8][2*w + 1] = rs_hi8;
            }
        }
        __syncthreads();

        // ============ Phase C: inverse-CDF sampling (unnormalized compares) ============
        const int li = lane & 15;
        #pragma unroll
        for (int j = 0; j < 2; ++j) {
            const int sa   = w * 4 + 2 * j;
            const int samp = (lane < 16) ? sa : (sa + 1);
            const int S    = Sblk + samp;

            float rowsum = s_rows[samp][li];
            float tot = rowsum;
            #pragma unroll
            for (int o = 1; o < 16; o <<= 1) tot += __shfl_xor_sync(FULLM, tot, o);

            float cdf = rowsum;
            #pragma unroll
            for (int d = 1; d < 16; d <<= 1) {
                float t = __shfl_up_sync(FULLM, cdf, d, 16);
                if (li >= d) cdf += t;
            }

            float u_x = __ldg(&wi[S*2]);
            float u_y = __ldg(&wi[S*2 + 1]);
            float uy  = u_y * tot;

            unsigned bal = __ballot_sync(FULLM, cdf < uy);
            unsigned mym = (lane < 16) ? (bal & 0xFFFFu) : (bal >> 16);
            int   iy   = min(__popc(mym), 15);
            float cdfp = __shfl_sync(FULLM, cdf, max(iy - 1, 0), 16);
            cdfp = (iy > 0) ? cdfp : 0.f;
            float py   = __shfl_sync(FULLM, rowsum, iy, 16);
            float yv   = ((float)iy + __fdividef(uy - cdfp, fmaxf(py, EPSF))) * 0.0625f;

            float hv   = s_hist[samp][iy*16 + li];
            float cdfx = hv;
            #pragma unroll
            for (int d = 1; d < 16; d <<= 1) {
                float t = __shfl_up_sync(FULLM, cdfx, d, 16);
                if (li >= d) cdfx += t;
            }
            float ux = u_x * py;
            unsigned balx = __ballot_sync(FULLM, cdfx < ux);
            unsigned mymx = (lane < 16) ? (balx & 0xFFFFu) : (balx >> 16);
            int   ix    = min(__popc(mymx), 15);
            float cdfxp = __shfl_sync(FULLM, cdfx, max(ix - 1, 0), 16);
            cdfxp = (ix > 0) ? cdfxp : 0.f;
            float px    = __shfl_sync(FULLM, hv, ix, 16);
            float xv    = ((float)ix + __fdividef(ux - cdfxp, fmaxf(px, EPSF))) * 0.0625f;
            float pout  = __fdividef(px, tot) * 64.f;

            if (li == 0) {
                out[S*2]       = xv * 2.f - 1.f;
                out[S*2 + 1]   = yv * 2.f - 1.f;
                out[2*BN + S]  = pout;
            }
        }
        __syncthreads();
    }
}

extern "C" void kernel_launch(void* const* d_in, const int* in_sizes, int n_in,
                              void* d_out, int out_size) {
    const float* wi   = (const float*)d_in[0];
    const float* cond = (const float*)d_in[1];
    const float* w0   = (const float*)d_in[2];
    const float* b0   = (const float*)d_in[3];
    const float* w1   = (const float*)d_in[4];
    const float* b1   = (const float*)d_in[5];
    const float* w2   = (const float*)d_in[6];
    const float* b2   = (const float*)d_in[7];
    const float* w3   = (const float*)d_in[8];
    const float* b3   = (const float*)d_in[9];
    (void)in_sizes; (void)n_in; (void)out_size;
    prep_kernel<<<21, 256>>>(w3, w0, w1, w2);
    hist2d_kernel<<<2048, 256>>>(wi, cond, b0, b1, b2, b3, (float*)d_out);
}

// round 15
// speedup vs baseline: 1.4886x; 1.4886x over previous
#include <cuda_runtime.h>
#include <cstdint>

#define FULLM 0xffffffffu
typedef unsigned long long ull;
typedef unsigned int uint;

static __device__ __forceinline__ ull mul2(ull a, ull b){
    ull d; asm("mul.rn.f32x2 %0, %1, %2;" : "=l"(d) : "l"(a), "l"(b)); return d;
}
static __device__ __forceinline__ ull dup2(float x){
    ull d; asm("mov.b64 %0, {%1, %1};" : "=l"(d) : "f"(x)); return d;
}
static __device__ __forceinline__ ull pack2(float a, float b){
    ull d; asm("mov.b64 %0, {%1, %2};" : "=l"(d) : "f"(a), "f"(b)); return d;
}
static __device__ __forceinline__ float2 unpk(ull a){
    float2 f; asm("mov.b64 {%0, %1}, %2;" : "=f"(f.x), "=f"(f.y) : "l"(a)); return f;
}
static __device__ __forceinline__ uint to_tf32(float x){
    uint r; asm("cvt.rna.tf32.f32 %0, %1;" : "=r"(r) : "f"(x)); return r;
}
static __device__ __forceinline__ void mma_tf32(float c[4], const uint a[4], uint b0, uint b1){
    asm("mma.sync.aligned.m16n8k8.row.col.f32.tf32.tf32.f32 "
        "{%0,%1,%2,%3}, {%4,%5,%6,%7}, {%8,%9}, {%0,%1,%2,%3};"
        : "+f"(c[0]), "+f"(c[1]), "+f"(c[2]), "+f"(c[3])
        : "r"(a[0]), "r"(a[1]), "r"(a[2]), "r"(a[3]), "r"(b0), "r"(b1));
}

// softplus via ex2 + lg2 (2 MUFU/elem, off the fma pipe)
static __device__ __forceinline__ float2 softplus2(ull x){
    ull ax; asm("and.b64 %0, %1, 0x7FFFFFFF7FFFFFFF;" : "=l"(ax) : "l"(x));
    ull t = mul2(ax, dup2(-1.4426950408889634f));
    float2 tf = unpk(t);
    float e0, e1;
    asm("ex2.approx.f32 %0, %1;" : "=f"(e0) : "f"(tf.x));
    asm("ex2.approx.f32 %0, %1;" : "=f"(e1) : "f"(tf.y));
    float l0, l1;
    asm("lg2.approx.f32 %0, %1;" : "=f"(l0) : "f"(e0 + 1.0f));
    asm("lg2.approx.f32 %0, %1;" : "=f"(l1) : "f"(e1 + 1.0f));
    float2 xf = unpk(x);
    return make_float2(fmaf(l0, 0.6931471805599453f, fmaxf(xf.x, 0.f)),
                       fmaf(l1, 0.6931471805599453f, fmaxf(xf.y, 0.f)));
}

constexpr int   BN     = 262144;
constexpr int   GROUPS = BN / 32;
constexpr int   HPAD   = 272;
constexpr int   AS     = 36;       // activation buffer stride (banks 4g+t all-distinct)
constexpr float EPSF   = 1e-12f;

// w3 fragments: [w][ik][j][lane] -> uint4 {bhi0,bhi1,blo0,blo1}
__device__ uint4 g_w3pack[8 * 4 * 4 * 32];
// w0/w1/w2 fragments: L0 [nt][ks(2)][lane] @0, L1 [nt][ks(4)][lane] @256, L2 @768
__device__ uint4 g_wfrag[1280];

__global__ void prep_kernel(const float* __restrict__ w3, const float* __restrict__ w0,
                            const float* __restrict__ w1, const float* __restrict__ w2) {
    int idx = blockIdx.x * blockDim.x + threadIdx.x;
    int lane = idx & 31;
    int gid = lane >> 2, tig = lane & 3;
    if (idx < 4096) {
        int j = (idx >> 5) & 3, ik = (idx >> 7) & 3, w = idx >> 9;
        int n0 = w * 32;
        float v0 = w3[(ik*8 + tig    )*256 + n0 + j*8 + gid];
        float v1 = w3[(ik*8 + tig + 4)*256 + n0 + j*8 + gid];
        uint h0 = to_tf32(v0), h1 = to_tf32(v1);
        g_w3pack[idx] = make_uint4(h0, h1, to_tf32(v0 - __uint_as_float(h0)),
                                           to_tf32(v1 - __uint_as_float(h1)));
    } else if (idx < 4096 + 256) {
        int t = idx - 4096;                     // L0: (nt*2 + ks)*32 + lane
        int ks = (t >> 5) & 1, nt = t >> 6;
        int n = nt*8 + gid;
        int ka = ks*8 + tig, kb = ks*8 + tig + 4;
        float v0 = (ka < 10) ? w0[ka*32 + n] : 0.f;
        float v1 = (kb < 10) ? w0[kb*32 + n] : 0.f;
        uint h0 = to_tf32(v0), h1 = to_tf32(v1);
        g_wfrag[t] = make_uint4(h0, h1, to_tf32(v0 - __uint_as_float(h0)),
                                        to_tf32(v1 - __uint_as_float(h1)));
    } else if (idx < 4096 + 256 + 1024) {
        int t = idx - 4096 - 256;               // L1/L2: (nt*4 + ks)*32 + lane
        const float* W = (t < 512) ? w1 : w2;
        int tt = t & 511;
        int ks = (tt >> 5) & 3, nt = tt >> 7;
        int n = nt*8 + gid;
        float v0 = W[(ks*8 + tig    )*32 + n];
        float v1 = W[(ks*8 + tig + 4)*32 + n];
        uint h0 = to_tf32(v0), h1 = to_tf32(v1);
        g_wfrag[256 + t] = make_uint4(h0, h1, to_tf32(v0 - __uint_as_float(h0)),
                                              to_tf32(v1 - __uint_as_float(h1)));
    }
}

__global__ __launch_bounds__(256, 3)
void hist2d_kernel(const float* __restrict__ wi, const float* __restrict__ cond,
                   const float* __restrict__ b0, const float* __restrict__ b1,
                   const float* __restrict__ b2, const float* __restrict__ b3,
                   float* __restrict__ out)
{
    __shared__ __align__(16) float bufA[32 * AS];
    __shared__ __align__(16) float bufB[32 * AS];
    __shared__ float s_rows[32][17];
    __shared__ __align__(16) float s_hist[32][HPAD];

    const int tid  = threadIdx.x;
    const int lane = tid & 31;
    const int w    = tid >> 5;
    const int gid  = lane >> 2;
    const int tig  = lane & 3;
    const int mt   = (w & 1) * 16;     // layer m-tile
    const int nt   = w >> 1;           // layer n-tile (0..3)
    const int n8   = nt * 8;
    const int n0   = w * 32;           // phase-B col base

    const float2 bs0 = make_float2(__ldg(&b0[n8 + 2*tig]), __ldg(&b0[n8 + 2*tig + 1]));
    const float2 bs1 = make_float2(__ldg(&b1[n8 + 2*tig]), __ldg(&b1[n8 + 2*tig + 1]));
    const float2 bs2 = make_float2(__ldg(&b2[n8 + 2*tig]), __ldg(&b2[n8 + 2*tig + 1]));
    float2 biasj[4];
    #pragma unroll
    for (int j = 0; j < 4; ++j) {
        biasj[j].x = __ldg(&b3[n0 + j*8 + 2*tig]);
        biasj[j].y = __ldg(&b3[n0 + j*8 + 2*tig + 1]);
    }
    const uint4* f0 = &g_wfrag[nt*64 + lane];
    const uint4* f1 = &g_wfrag[256 + nt*128 + lane];
    const uint4* f2 = &g_wfrag[768 + nt*128 + lane];
    const uint4* fragp = &g_w3pack[(w * 16) * 32 + lane];

    // one MLP layer (m16n8 tile per warp) via 3xTF32 mma, relu, write to dst
    auto layer = [&](const float* src, float* dst, const uint4* wf, float2 bs, int ksteps) {
        float c[4] = {0.f, 0.f, 0.f, 0.f};
        #pragma unroll 4
        for (int ks = 0; ks < ksteps; ++ks) {
            const int k0 = ks * 8;
            float a0 = src[(mt + gid    ) * AS + k0 + tig    ];
            float a1 = src[(mt + gid + 8) * AS + k0 + tig    ];
            float a2 = src[(mt + gid    ) * AS + k0 + tig + 4];
            float a3 = src[(mt + gid + 8) * AS + k0 + tig + 4];
            uint ah[4], al[4];
            ah[0] = to_tf32(a0); al[0] = to_tf32(a0 - __uint_as_float(ah[0]));
            ah[1] = to_tf32(a1); al[1] = to_tf32(a1 - __uint_as_float(ah[1]));
            ah[2] = to_tf32(a2); al[2] = to_tf32(a2 - __uint_as_float(ah[2]));
            ah[3] = to_tf32(a3); al[3] = to_tf32(a3 - __uint_as_float(ah[3]));
            uint4 f = __ldg(&wf[ks * 32]);
            mma_tf32(c, ah, f.x, f.y);
            mma_tf32(c, ah, f.z, f.w);
            mma_tf32(c, al, f.x, f.y);
        }
        c[0] = fmaxf(c[0] + bs.x, 0.f);
        c[1] = fmaxf(c[1] + bs.y, 0.f);
        c[2] = fmaxf(c[2] + bs.x, 0.f);
        c[3] = fmaxf(c[3] + bs.y, 0.f);
        *(float2*)&dst[(mt + gid    ) * AS + n8 + 2*tig] = make_float2(c[0], c[1]);
        *(float2*)&dst[(mt + gid + 8) * AS + n8 + 2*tig] = make_float2(c[2], c[3]);
    };

    for (int g = blockIdx.x; g < GROUPS; g += gridDim.x) {
        const int Sblk = g * 32;

        // ---- load cond into bufA (strided: 320 > blockDim) + zero-pad K 10..15 ----
        #pragma unroll
        for (int i = tid; i < 320; i += 256) bufA[(i/10)*AS + (i%10)] = __ldg(&cond[Sblk*10 + i]);
        if (tid < 192) bufA[(tid/6)*AS + 10 + (tid%6)] = 0.f;
        __syncthreads();

        layer(bufA, bufB, f0, bs0, 2);   // 10(16) -> 32
        __syncthreads();
        layer(bufB, bufA, f1, bs1, 4);   // 32 -> 32
        __syncthreads();
        layer(bufA, bufB, f2, bs2, 4);   // 32 -> 32
        __syncthreads();

        // ============ Phase B: layer 3 via mma tf32, ik outer / im inner ============
        float c[2][4][4];
        #pragma unroll
        for (int im = 0; im < 2; ++im)
            #pragma unroll
            for (int j = 0; j < 4; ++j) {
                c[im][j][0] = biasj[j].x; c[im][j][1] = biasj[j].y;
                c[im][j][2] = biasj[j].x; c[im][j][3] = biasj[j].y;
            }

        #pragma unroll
        for (int ik = 0; ik < 4; ++ik) {
            const int k0 = ik * 8;
            uint ah[2][4], al[2][4];
            #pragma unroll
            for (int im = 0; im < 2; ++im) {
                const int r0 = im * 16 + gid;
                float a0 = bufB[ r0      * AS + k0 + tig    ];
                float a1 = bufB[(r0 + 8) * AS + k0 + tig    ];
                float a2 = bufB[ r0      * AS + k0 + tig + 4];
                float a3 = bufB[(r0 + 8) * AS + k0 + tig + 4];
                ah[im][0] = to_tf32(a0); al[im][0] = to_tf32(a0 - __uint_as_float(ah[im][0]));
                ah[im][1] = to_tf32(a1); al[im][1] = to_tf32(a1 - __uint_as_float(ah[im][1]));
                ah[im][2] = to_tf32(a2); al[im][2] = to_tf32(a2 - __uint_as_float(ah[im][2]));
                ah[im][3] = to_tf32(a3); al[im][3] = to_tf32(a3 - __uint_as_float(ah[im][3]));
            }
            #pragma unroll
            for (int j = 0; j < 4; ++j) {
                uint4 f = __ldg(&fragp[(ik*4 + j) * 32]);
                #pragma unroll
                for (int im = 0; im < 2; ++im) {
                    mma_tf32(c[im][j], ah[im], f.x, f.y);
                    mma_tf32(c[im][j], ah[im], f.z, f.w);
                    mma_tf32(c[im][j], al[im], f.x, f.y);
                }
            }
        }

        // epilogue: softplus, hist writes, row sums
        #pragma unroll
        for (int im = 0; im < 2; ++im) {
            const int m0 = im * 16 + gid;
            float rs_lo0 = 0.f, rs_hi0 = 0.f, rs_lo8 = 0.f, rs_hi8 = 0.f;
            #pragma unroll
            for (int j = 0; j < 4; ++j) {
                float2 s01 = softplus2(pack2(c[im][j][0], c[im][j][1]));
                float2 s23 = softplus2(pack2(c[im][j][2], c[im][j][3]));
                const int colb = n0 + j*8 + 2*tig;
                *(float2*)&s_hist[m0    ][colb] = s01;
                *(float2*)&s_hist[m0 + 8][colb] = s23;
                float t0 = s01.x + s01.y;
                float t8 = s23.x + s23.y;
                if (j < 2) { rs_lo0 += t0; rs_lo8 += t8; }
                else       { rs_hi0 += t0; rs_hi8 += t8; }
            }
            rs_lo0 += __shfl_xor_sync(FULLM, rs_lo0, 1);
            rs_hi0 += __shfl_xor_sync(FULLM, rs_hi0, 1);
            rs_lo8 += __shfl_xor_sync(FULLM, rs_lo8, 1);
            rs_hi8 += __shfl_xor_sync(FULLM, rs_hi8, 1);
            rs_lo0 += __shfl_xor_sync(FULLM, rs_lo0, 2);
            rs_hi0 += __shfl_xor_sync(FULLM, rs_hi0, 2);
            rs_lo8 += __shfl_xor_sync(FULLM, rs_lo8, 2);
            rs_hi8 += __shfl_xor_sync(FULLM, rs_hi8, 2);
            if (tig == 0) {
                s_rows[m0    ][2*w    ] = rs_lo0;
                s_rows[m0    ][2*w + 1] = rs_hi0;
                s_rows[m0 + 8][2*w    ] = rs_lo8;
                s_rows[m0 + 8][2*w + 1] = rs_hi8;
            }
        }
        __syncthreads();

        // ============ Phase C: inverse-CDF sampling (unnormalized compares) ============
        const int li = lane & 15;
        #pragma unroll
        for (int j = 0; j < 2; ++j) {
            const int sa   = w * 4 + 2 * j;
            const int samp = (lane < 16) ? sa : (sa + 1);
            const int S    = Sblk + samp;

            // hoisted: DRAM-latency loads overlap the scan chains below
            float u_x = __ldg(&wi[S*2]);
            float u_y = __ldg(&wi[S*2 + 1]);

            float rowsum = s_rows[samp][li];
            float cdf = rowsum;
            #pragma unroll
            for (int d = 1; d < 16; d <<= 1) {
                float t = __shfl_up_sync(FULLM, cdf, d, 16);
                if (li >= d) cdf += t;
            }
            // total = inclusive scan at lane 15 (replaces 4-shfl butterfly)
            float tot = __shfl_sync(FULLM, cdf, 15, 16);
            float uy  = u_y * tot;

            unsigned bal = __ballot_sync(FULLM, cdf < uy);
            unsigned mym = (lane < 16) ? (bal & 0xFFFFu) : (bal >> 16);
            int   iy   = min(__popc(mym), 15);
            float cdfp = __shfl_sync(FULLM, cdf, max(iy - 1, 0), 16);
            cdfp = (iy > 0) ? cdfp : 0.f;
            float py   = __shfl_sync(FULLM, rowsum, iy, 16);
            float yv   = ((float)iy + __fdividef(uy - cdfp, fmaxf(py, EPSF))) * 0.0625f;

            float hv   = s_hist[samp][iy*16 + li];
            float cdfx = hv;
            #pragma unroll
            for (int d = 1; d < 16; d <<= 1) {
                float t = __shfl_up_sync(FULLM, cdfx, d, 16);
                if (li >= d) cdfx += t;
            }
            float ux = u_x * py;
            unsigned balx = __ballot_sync(FULLM, cdfx < ux);
            unsigned mymx = (lane < 16) ? (balx & 0xFFFFu) : (balx >> 16);
            int   ix    = min(__popc(mymx), 15);
            float cdfxp = __shfl_sync(FULLM, cdfx, max(ix - 1, 0), 16);
            cdfxp = (ix > 0) ? cdfxp : 0.f;
            float px    = __shfl_sync(FULLM, hv, ix, 16);
            float xv    = ((float)ix + __fdividef(ux - cdfxp, fmaxf(px, EPSF))) * 0.0625f;
            float pout  = __fdividef(px, tot) * 64.f;

            if (li == 0) {
                out[S*2]       = xv * 2.f - 1.f;
                out[S*2 + 1]   = yv * 2.f - 1.f;
                out[2*BN + S]  = pout;
            }
        }
        __syncthreads();   // s_hist consumed before next group's phase-B epilogue
    }
}

extern "C" void kernel_launch(void* const* d_in, const int* in_sizes, int n_in,
                              void* d_out, int out_size) {
    const float* wi   = (const float*)d_in[0];
    const float* cond = (const float*)d_in[1];
    const float* w0   = (const float*)d_in[2];
    const float* b0   = (const float*)d_in[3];
    const float* w1   = (const float*)d_in[4];
    const float* b1   = (const float*)d_in[5];
    const float* w2   = (const float*)d_in[6];
    const float* b2   = (const float*)d_in[7];
    const float* w3   = (const float*)d_in[8];
    const float* b3   = (const float*)d_in[9];
    (void)in_sizes; (void)n_in; (void)out_size;
    prep_kernel<<<21, 256>>>(w3, w0, w1, w2);
    hist2d_kernel<<<2048, 256>>>(wi, cond, b0, b1, b2, b3, (float*)d_out);
}